// round 16
// baseline (speedup 1.0000x reference)
#include <cuda_runtime.h>
#include <cuda_fp16.h>
#include <math.h>
#include <stdint.h>

#define T 2048
#define H 2048
#define NH 32
#define NKV 8
#define HD 64
#define FFN 4096
#define NE 8
#define QKV_N 3072
#define ASSIGN (2*T)

// ---------------- scratch ----------------------------------------------------
__device__ float g_xnorm[T*H];
__device__ float g_qkv[(long)T*QKV_N];
__device__ float g_attn[(long)T*H];
__device__ float g_x2[(long)T*H];
__device__ float g_h1[(long)ASSIGN*FFN];
__device__ float g_h3[(long)ASSIGN*FFN];
__device__ float g_y[(long)ASSIGN*H];
__device__ int   g_counts[NE];
__device__ int   g_offs[NE];
__device__ int   g_fill[NE];
__device__ int   g_perm[ASSIGN];
__device__ float g_permw[ASSIGN];
__device__ int   g_tokpos[ASSIGN];
__device__ int   g_topid[T*2];
__device__ float g_topw[T*2];

// ---------------- helpers ------------------------------------------------------
__device__ __forceinline__ void mma_f16(float* c, const uint32_t* a, const uint32_t* b) {
    asm volatile(
        "mma.sync.aligned.m16n8k16.row.col.f32.f16.f16.f32 "
        "{%0,%1,%2,%3},{%4,%5,%6,%7},{%8,%9},{%0,%1,%2,%3};"
        : "+f"(c[0]), "+f"(c[1]), "+f"(c[2]), "+f"(c[3])
        : "r"(a[0]), "r"(a[1]), "r"(a[2]), "r"(a[3]), "r"(b[0]), "r"(b[1]));
}
__device__ __forceinline__ uint32_t packh2(float lo, float hi) {
    __half2 h = __floats2half2_rn(lo, hi);
    return *(uint32_t*)&h;
}
__device__ __forceinline__ uint32_t smem_u32(const void* p) {
    uint32_t a;
    asm("{ .reg .u64 t; cvta.to.shared.u64 t, %1; cvt.u32.u64 %0, t; }" : "=r"(a) : "l"(p));
    return a;
}

// ---------------- rmsnorm ------------------------------------------------------
__global__ __launch_bounds__(256) void rmsnorm_kernel(
    const float* __restrict__ x, const float* __restrict__ w, float* __restrict__ out)
{
    int t = blockIdx.x;
    const float* xr = x + (long)t*H;
    __shared__ float red[256];
    float s = 0.f;
    for (int h = threadIdx.x; h < H; h += 256) { float v = xr[h]; s += v*v; }
    red[threadIdx.x] = s; __syncthreads();
    for (int st = 128; st > 0; st >>= 1) {
        if (threadIdx.x < st) red[threadIdx.x] += red[threadIdx.x+st];
        __syncthreads();
    }
    float inv = rsqrtf(red[0]/(float)H + 1e-5f);
    float* orow = out + (long)t*H;
    for (int h = threadIdx.x; h < H; h += 256) orow[h] = xr[h]*inv*w[h];
}

// ---------------- rmsnorm + router (fused, bit-identical) -----------------------
__global__ __launch_bounds__(256) void rmsnorm_router_kernel(
    const float* __restrict__ x, const float* __restrict__ w,
    const float* __restrict__ gw, float* __restrict__ out)
{
    int t = blockIdx.x;
    const float* xr = x + (long)t*H;
    __shared__ float red[256];
    float s = 0.f;
    for (int h = threadIdx.x; h < H; h += 256) { float v = xr[h]; s += v*v; }
    red[threadIdx.x] = s; __syncthreads();
    for (int st = 128; st > 0; st >>= 1) {
        if (threadIdx.x < st) red[threadIdx.x] += red[threadIdx.x+st];
        __syncthreads();
    }
    float inv = rsqrtf(red[0]/(float)H + 1e-5f);
    __syncthreads();

    float* orow = out + (long)t*H;
    float p[NE] = {};
    for (int h = threadIdx.x; h < H; h += 256) {
        float v = xr[h]*inv*w[h];
        orow[h] = v;
        #pragma unroll
        for (int e = 0; e < NE; e++) p[e] += v * gw[h*NE + e];
    }
    __shared__ float red8[NE*256];
    #pragma unroll
    for (int e = 0; e < NE; e++) red8[e*256 + threadIdx.x] = p[e];
    __syncthreads();
    for (int st = 128; st > 0; st >>= 1) {
        if (threadIdx.x < st)
            #pragma unroll
            for (int e = 0; e < NE; e++)
                red8[e*256+threadIdx.x] += red8[e*256+threadIdx.x+st];
        __syncthreads();
    }
    if (threadIdx.x == 0) {
        float l[NE];
        #pragma unroll
        for (int e = 0; e < NE; e++) l[e] = red8[e*256];
        int i1 = 0;
        #pragma unroll
        for (int e = 1; e < NE; e++) if (l[e] > l[i1]) i1 = e;
        int i2 = -1;
        #pragma unroll
        for (int e = 0; e < NE; e++) if (e != i1 && (i2 < 0 || l[e] > l[i2])) i2 = e;
        float p2 = expf(l[i2] - l[i1]);
        float invw = 1.f / (1.f + p2);
        g_topid[2*t] = i1;   g_topid[2*t+1] = i2;
        g_topw[2*t]  = invw; g_topw[2*t+1]  = p2*invw;
        atomicAdd(&g_counts[i1], 1);
        atomicAdd(&g_counts[i2], 1);
    }
}

// ---------------- fp16 mma.sync GEMM: 128x128 CTA, 4 warps (2x2), 64x64 tiles ---
#define PAW 18
#define PBW 18
#define A10_WORDS (128*PAW)
#define B10_WORDS (128*PBW)
#define G10_SMEM ((2*(A10_WORDS+B10_WORDS))*4)

template<int MODE>
__global__ __launch_bounds__(128, 2) void gemm10(
    const float* __restrict__ A, const float* __restrict__ B, float* __restrict__ C,
    int M, int N, int K, const float* __restrict__ addsrc, long bStrideZ,
    const float* __restrict__ B3, float* __restrict__ C3)
{
    extern __shared__ uint32_t sm10[];
    int z = blockIdx.z;
    int mBase = blockIdx.y * 128;
    int nBase = blockIdx.x * 128;
    int Meff = M, rowOff = 0;
    if (MODE == 1 || MODE == 2) {
        int ze = (MODE == 1 && z >= NE) ? z - NE : z;
        if (MODE == 1 && z >= NE) { B = B3; C = C3; }
        Meff = g_counts[ze]; rowOff = g_offs[ze];
        if (mBase >= Meff) return;
        B += (long)ze * bStrideZ;
    }

    int tid = threadIdx.x, lane = tid & 31, wid = tid >> 5;
    int mW = (wid >> 1) * 64;
    int nW = (wid & 1) * 64;
    int g  = lane >> 2, t4 = lane & 3;

    uint32_t* smA = sm10;
    uint32_t* smB = sm10 + 2*A10_WORDS;

    int arow = tid >> 3;
    int ac   = tid & 7;
    const float* aPtr[8]; bool aOk[8];
    #pragma unroll
    for (int i = 0; i < 8; i++) {
        int gm = mBase + arow + 16*i;
        aOk[i] = gm < Meff;
        long r;
        if (MODE == 1)      r = aOk[i] ? (long)g_perm[rowOff + gm] : 0;
        else if (MODE == 2) r = (long)(rowOff + (aOk[i] ? gm : 0));
        else                r = (long)(aOk[i] ? gm : 0);
        aPtr[i] = A + r*(long)K + ac*4;
    }
    int nl = tid & 31;
    int kp = tid >> 5;
    const float* bPtr = B + nBase + nl;

    float acc[4][8][4];
    #pragma unroll
    for (int mt = 0; mt < 4; mt++)
        #pragma unroll
        for (int nt = 0; nt < 8; nt++)
            #pragma unroll
            for (int q = 0; q < 4; q++) acc[mt][nt][q] = 0.f;

    int KT = K >> 5;
    float4 aR[8];
    float bv0[4][4], bv1[4][4];

    #pragma unroll
    for (int i = 0; i < 8; i++)
        aR[i] = aOk[i] ? *(const float4*)(aPtr[i]) : make_float4(0.f,0.f,0.f,0.f);
    #pragma unroll
    for (int p = 0; p < 4; p++)
        #pragma unroll
        for (int j = 0; j < 4; j++) {
            long ko = (long)(2*(kp + 4*p))*N + 32*j;
            bv0[p][j] = bPtr[ko];
            bv1[p][j] = bPtr[ko + N];
        }
    #pragma unroll
    for (int i = 0; i < 8; i++) {
        uint2 u = { packh2(aR[i].x, aR[i].y), packh2(aR[i].z, aR[i].w) };
        *(uint2*)(smA + (arow + 16*i)*PAW + ac*2) = u;
    }
    #pragma unroll
    for (int p = 0; p < 4; p++)
        #pragma unroll
        for (int j = 0; j < 4; j++)
            smB[(nl + 32*j)*PBW + kp + 4*p] = packh2(bv0[p][j], bv1[p][j]);
    __syncthreads();

    for (int kt = 0; kt < KT; kt++) {
        int buf = kt & 1;
        int nb  = buf ^ 1;
        if (kt + 1 < KT) {
            int k0 = (kt + 1) << 5;
            #pragma unroll
            for (int i = 0; i < 8; i++)
                aR[i] = aOk[i] ? *(const float4*)(aPtr[i] + k0)
                               : make_float4(0.f,0.f,0.f,0.f);
            #pragma unroll
            for (int p = 0; p < 4; p++)
                #pragma unroll
                for (int j = 0; j < 4; j++) {
                    long ko = (long)(k0 + 2*(kp + 4*p))*N + 32*j;
                    bv0[p][j] = bPtr[ko];
                    bv1[p][j] = bPtr[ko + N];
                }
        }

        const uint32_t* as = smA + buf*A10_WORDS;
        const uint32_t* bs = smB + buf*B10_WORDS;

        #pragma unroll
        for (int s = 0; s < 2; s++) {
            uint32_t af[4][4], bf[8][2];
            #pragma unroll
            for (int mt = 0; mt < 4; mt++) {
                const uint32_t* p = as + (mW + mt*16 + g)*PAW + s*8 + t4;
                af[mt][0] = p[0];
                af[mt][1] = p[8*PAW];
                af[mt][2] = p[4];
                af[mt][3] = p[8*PAW + 4];
            }
            #pragma unroll
            for (int nt = 0; nt < 8; nt++) {
                const uint32_t* p = bs + (nW + nt*8 + g)*PBW + s*8 + t4;
                bf[nt][0] = p[0];
                bf[nt][1] = p[4];
            }
            #pragma unroll
            for (int mt = 0; mt < 4; mt++)
                #pragma unroll
                for (int nt = 0; nt < 8; nt++)
                    mma_f16(acc[mt][nt], af[mt], bf[nt]);
        }

        if (kt + 1 < KT) {
            uint32_t* dA = smA + nb*A10_WORDS;
            uint32_t* dB = smB + nb*B10_WORDS;
            #pragma unroll
            for (int i = 0; i < 8; i++) {
                uint2 u = { packh2(aR[i].x, aR[i].y), packh2(aR[i].z, aR[i].w) };
                *(uint2*)(dA + (arow + 16*i)*PAW + ac*2) = u;
            }
            #pragma unroll
            for (int p = 0; p < 4; p++)
                #pragma unroll
                for (int j = 0; j < 4; j++)
                    dB[(nl + 32*j)*PBW + kp + 4*p] = packh2(bv0[p][j], bv1[p][j]);
        }
        __syncthreads();
    }

    #pragma unroll
    for (int mt = 0; mt < 4; mt++) {
        #pragma unroll
        for (int half = 0; half < 2; half++) {
            int rRel = mW + mt*16 + g + half*8;
            bool ok = (MODE == 0) || (mBase + rRel < Meff);
            if (!ok) continue;
            long crow;
            float scale = 1.f;
            if (MODE == 0) crow = (long)(mBase + rRel);
            else           crow = (long)(rowOff + mBase + rRel);
            if (MODE == 2) scale = g_permw[rowOff + mBase + rRel];
            #pragma unroll
            for (int nt = 0; nt < 8; nt++) {
                int col = nBase + nW + nt*8 + t4*2;
                float v0 = acc[mt][nt][2*half + 0];
                float v1 = acc[mt][nt][2*half + 1];
                if (MODE == 2) { v0 *= scale; v1 *= scale; }
                if (MODE == 0 && addsrc) {
                    v0 += addsrc[crow*N + col];
                    v1 += addsrc[crow*N + col + 1];
                }
                *(float2*)(C + crow*N + col) = make_float2(v0, v1);
            }
        }
    }
}

// ---------------- RoPE (smem sincos table) --------------------------------------
__global__ __launch_bounds__(256) void rope_kernel(float* __restrict__ qkv)
{
    __shared__ float cs[32], sn[32];
    int t = blockIdx.x;
    float pos = (float)t;
    if (threadIdx.x < 32) {
        int j = threadIdx.x;
        float inv = expf(-((float)(2*j)/(float)HD) * logf(10000.0f));
        float f = pos * inv;
        cs[j] = cosf(f);
        sn[j] = sinf(f);
    }
    __syncthreads();
    for (int idx = threadIdx.x; idx < (NH+NKV)*32; idx += 256) {
        int head = idx >> 5;
        int j    = idx & 31;
        int colbase = (head < NH) ? head*HD : (NH*HD + (head-NH)*HD);
        float c = cs[j], s = sn[j];
        float* p = qkv + (long)t*QKV_N + colbase;
        float x1 = p[j], x2 = p[j+32];
        p[j]    = x1*c - x2*s;
        p[j+32] = x2*c + x1*s;
    }
}

// ---------------- flash attention: 128 q-rows/CTA, split-fp16 QK^T, fp16 PV ----
// 8 warps x 16 q-rows. K/V staging amortized over 2x more MMA work.
#define PH  36
#define PVW 35
#define PP  36
#define ATTN_SMEM ((2*128*PH + 2*64*PH + 64*PVW + 128*PP)*4)

__global__ __launch_bounds__(256, 2) void attn_tc_kernel(
    const float* __restrict__ qkv, float* __restrict__ attn)
{
    extern __shared__ uint32_t su[];
    uint32_t* sQh = su;                    // 128 x PH
    uint32_t* sQl = sQh + 128*PH;          // 128 x PH
    uint32_t* sKh = sQl + 128*PH;          // 64 x PH
    uint32_t* sKl = sKh + 64*PH;           // 64 x PH
    uint32_t* sVt = sKl + 64*PH;           // 64 x PVW  ([d][key-pair])
    uint32_t* sP  = sVt + 64*PVW;          // 128 x PP
    __half*   sVtH = (__half*)sVt;

    int h = blockIdx.y, qt = blockIdx.x;   // q rows [qt*128, qt*128+128)
    int kvh = h >> 2;
    int tid = threadIdx.x, lane = tid & 31, w = tid >> 5;
    int g = lane >> 2, t4 = lane & 3;
    int mRow = w*16 + g;                   // 0..127

    // ---- load Q (scaled), split fp16 hi/lo ----
    for (int i = tid; i < 2048; i += 256) {
        int r = i >> 4, d4 = (i & 15) << 2;
        float4 v = *(const float4*)(qkv + (long)(qt*128 + r)*QKV_N + h*HD + d4);
        float q0 = v.x*0.125f, q1 = v.y*0.125f, q2 = v.z*0.125f, q3 = v.w*0.125f;
        __half h0 = __float2half_rn(q0), h1 = __float2half_rn(q1);
        __half h2 = __float2half_rn(q2), h3 = __float2half_rn(q3);
        float l0 = q0 - __half2float(h0), l1 = q1 - __half2float(h1);
        float l2 = q2 - __half2float(h2), l3 = q3 - __half2float(h3);
        __half2 p0 = __halves2half2(h0, h1), p1 = __halves2half2(h2, h3);
        uint2 uh = { *(uint32_t*)&p0, *(uint32_t*)&p1 };
        uint2 ul = { packh2(l0, l1), packh2(l2, l3) };
        *(uint2*)(sQh + r*PH + (d4 >> 1)) = uh;
        *(uint2*)(sQl + r*PH + (d4 >> 1)) = ul;
    }

    float m_a = -1e30f, m_b = -1e30f, l_a = 0.f, l_b = 0.f;
    float o[8][4];
    #pragma unroll
    for (int nt = 0; nt < 8; nt++)
        #pragma unroll
        for (int q = 0; q < 4; q++) o[nt][q] = 0.f;

    int ktEnd = 2*qt + 1;                  // keys up to (qt+1)*128
    for (int kt = 0; kt <= ktEnd; kt++) {
        __syncthreads();
        for (int i = tid; i < 1024; i += 256) {
            int r = i >> 4, d4 = (i & 15) << 2;
            const float* kp = qkv + (long)(kt*64 + r)*QKV_N + NH*HD + kvh*HD + d4;
            float4 kv = *(const float4*)kp;
            float4 vv = *(const float4*)(kp + NKV*HD);
            __half h0 = __float2half_rn(kv.x), h1 = __float2half_rn(kv.y);
            __half h2 = __float2half_rn(kv.z), h3 = __float2half_rn(kv.w);
            float l0 = kv.x - __half2float(h0), l1 = kv.y - __half2float(h1);
            float l2 = kv.z - __half2float(h2), l3 = kv.w - __half2float(h3);
            __half2 p0 = __halves2half2(h0, h1), p1 = __halves2half2(h2, h3);
            uint2 uh = { *(uint32_t*)&p0, *(uint32_t*)&p1 };
            uint2 ul = { packh2(l0, l1), packh2(l2, l3) };
            *(uint2*)(sKh + r*PH + (d4 >> 1)) = uh;
            *(uint2*)(sKl + r*PH + (d4 >> 1)) = ul;
            sVtH[(d4+0)*(2*PVW) + r] = __float2half_rn(vv.x);
            sVtH[(d4+1)*(2*PVW) + r] = __float2half_rn(vv.y);
            sVtH[(d4+2)*(2*PVW) + r] = __float2half_rn(vv.z);
            sVtH[(d4+3)*(2*PVW) + r] = __float2half_rn(vv.w);
        }
        __syncthreads();

        float s[8][4];
        #pragma unroll
        for (int nt = 0; nt < 8; nt++)
            #pragma unroll
            for (int q = 0; q < 4; q++) s[nt][q] = 0.f;

        #pragma unroll
        for (int ks = 0; ks < 4; ks++) {
            uint32_t ah[4], al[4];
            {
                const uint32_t* p = sQh + mRow*PH + ks*8 + t4;
                ah[0]=p[0]; ah[1]=p[8*PH]; ah[2]=p[4]; ah[3]=p[8*PH+4];
                const uint32_t* q2 = sQl + mRow*PH + ks*8 + t4;
                al[0]=q2[0]; al[1]=q2[8*PH]; al[2]=q2[4]; al[3]=q2[8*PH+4];
            }
            #pragma unroll
            for (int nt = 0; nt < 8; nt++) {
                uint32_t bh[2], bl[2];
                const uint32_t* p = sKh + (nt*8 + g)*PH + ks*8 + t4;
                bh[0] = p[0]; bh[1] = p[4];
                const uint32_t* q2 = sKl + (nt*8 + g)*PH + ks*8 + t4;
                bl[0] = q2[0]; bl[1] = q2[4];
                mma_f16(s[nt], ah, bh);
                mma_f16(s[nt], ah, bl);
                mma_f16(s[nt], al, bh);
            }
        }

        // causal mask: global col kt*64+c vs global row qt*128+r
        if (kt >= 2*qt) {
            int rowA = qt*128 + mRow;
            int rowB = rowA + 8;
            #pragma unroll
            for (int nt = 0; nt < 8; nt++) {
                int c0 = kt*64 + nt*8 + 2*t4;
                if (c0     > rowA) s[nt][0] = -1e30f;
                if (c0 + 1 > rowA) s[nt][1] = -1e30f;
                if (c0     > rowB) s[nt][2] = -1e30f;
                if (c0 + 1 > rowB) s[nt][3] = -1e30f;
            }
        }

        float rma = -1e30f, rmb = -1e30f;
        #pragma unroll
        for (int nt = 0; nt < 8; nt++) {
            rma = fmaxf(rma, fmaxf(s[nt][0], s[nt][1]));
            rmb = fmaxf(rmb, fmaxf(s[nt][2], s[nt][3]));
        }
        rma = fmaxf(rma, __shfl_xor_sync(0xffffffffu, rma, 1));
        rma = fmaxf(rma, __shfl_xor_sync(0xffffffffu, rma, 2));
        rmb = fmaxf(rmb, __shfl_xor_sync(0xffffffffu, rmb, 1));
        rmb = fmaxf(rmb, __shfl_xor_sync(0xffffffffu, rmb, 2));

        float mna = fmaxf(m_a, rma), mnb = fmaxf(m_b, rmb);
        float suma = 0.f, sumb = 0.f;
        #pragma unroll
        for (int nt = 0; nt < 8; nt++) {
            s[nt][0] = __expf(s[nt][0] - mna); suma += s[nt][0];
            s[nt][1] = __expf(s[nt][1] - mna); suma += s[nt][1];
            s[nt][2] = __expf(s[nt][2] - mnb); sumb += s[nt][2];
            s[nt][3] = __expf(s[nt][3] - mnb); sumb += s[nt][3];
        }
        suma += __shfl_xor_sync(0xffffffffu, suma, 1);
        suma += __shfl_xor_sync(0xffffffffu, suma, 2);
        sumb += __shfl_xor_sync(0xffffffffu, sumb, 1);
        sumb += __shfl_xor_sync(0xffffffffu, sumb, 2);

        float alpa = __expf(m_a - mna), alpb = __expf(m_b - mnb);
        l_a = l_a*alpa + suma; m_a = mna;
        l_b = l_b*alpb + sumb; m_b = mnb;
        #pragma unroll
        for (int nt = 0; nt < 8; nt++) {
            o[nt][0] *= alpa; o[nt][1] *= alpa;
            o[nt][2] *= alpb; o[nt][3] *= alpb;
        }

        #pragma unroll
        for (int nt = 0; nt < 8; nt++) {
            sP[mRow*PP + nt*4 + t4]     = packh2(s[nt][0], s[nt][1]);
            sP[(mRow+8)*PP + nt*4 + t4] = packh2(s[nt][2], s[nt][3]);
        }
        __syncwarp();

        #pragma unroll
        for (int ks = 0; ks < 4; ks++) {
            uint32_t ap[4];
            const uint32_t* p = sP + mRow*PP + ks*8 + t4;
            ap[0]=p[0]; ap[1]=p[8*PP]; ap[2]=p[4]; ap[3]=p[8*PP+4];
            #pragma unroll
            for (int nt = 0; nt < 8; nt++) {
                uint32_t bv[2];
                const uint32_t* q = sVt + (nt*8 + g)*PVW + ks*8 + t4;
                bv[0] = q[0]; bv[1] = q[4];
                mma_f16(o[nt], ap, bv);
            }
        }
    }

    float inva = 1.f / l_a, invb = 1.f / l_b;
    #pragma unroll
    for (int nt = 0; nt < 8; nt++) {
        int col = h*HD + nt*8 + 2*t4;
        long ra = (long)(qt*128 + mRow);
        *(float2*)(attn + ra*H + col)     = make_float2(o[nt][0]*inva, o[nt][1]*inva);
        *(float2*)(attn + (ra+8)*H + col) = make_float2(o[nt][2]*invb, o[nt][3]*invb);
    }
}

// ---------------- MoE plumbing --------------------------------------------------
__global__ void reset_kernel() { if (threadIdx.x < NE) g_counts[threadIdx.x] = 0; }

__global__ void scan_kernel() {
    if (threadIdx.x == 0) {
        int s = 0;
        for (int e = 0; e < NE; e++) { g_offs[e] = s; g_fill[e] = s; s += g_counts[e]; }
    }
}

__global__ void scatter_kernel() {
    int t = blockIdx.x*256 + threadIdx.x;
    if (t >= T) return;
    #pragma unroll
    for (int k = 0; k < 2; k++) {
        int e = g_topid[2*t+k];
        int pos = atomicAdd(&g_fill[e], 1);
        g_perm[pos]  = t;
        g_permw[pos] = g_topw[2*t+k];
        g_tokpos[2*t+k] = pos;
    }
}

__global__ __launch_bounds__(256) void silu_kernel() {
    long n = (long)ASSIGN*FFN;
    for (long i = (long)blockIdx.x*256 + threadIdx.x; i < n; i += (long)gridDim.x*256) {
        float a = g_h1[i];
        g_h1[i] = (a / (1.f + expf(-a))) * g_h3[i];
    }
}

__global__ __launch_bounds__(256) void combine_kernel(float* __restrict__ out) {
    int idx = blockIdx.x*256 + threadIdx.x;
    int t = idx >> 11;
    int c = idx & (H-1);
    out[idx] = g_y[(long)g_tokpos[2*t]*H + c] + g_y[(long)g_tokpos[2*t+1]*H + c];
}

// ---------------- launch --------------------------------------------------------
extern "C" void kernel_launch(void* const* d_in, const int* in_sizes, int n_in,
                              void* d_out, int out_size)
{
    const float* hidden = (const float*)d_in[0];
    const float* w_qkv  = (const float*)d_in[2];
    const float* w_o    = (const float*)d_in[3];
    const float* gate_w = (const float*)d_in[4];
    const float* w1     = (const float*)d_in[5];
    const float* w2     = (const float*)d_in[6];
    const float* w3     = (const float*)d_in[7];
    const float* ln1    = (const float*)d_in[8];
    const float* ln2    = (const float*)d_in[9];

    float* out       = (float*)d_out;
    float* final_out = out;
    float* resid_out = out + (long)T*H;

    float *xnorm, *qkvb, *attnb, *x2, *h1, *h3, *y;
    cudaGetSymbolAddress((void**)&xnorm, g_xnorm);
    cudaGetSymbolAddress((void**)&qkvb,  g_qkv);
    cudaGetSymbolAddress((void**)&attnb, g_attn);
    cudaGetSymbolAddress((void**)&x2,    g_x2);
    cudaGetSymbolAddress((void**)&h1,    g_h1);
    cudaGetSymbolAddress((void**)&h3,    g_h3);
    cudaGetSymbolAddress((void**)&y,     g_y);

    static bool attrDone = false;
    if (!attrDone) {
        cudaFuncSetAttribute(gemm10<0>, cudaFuncAttributeMaxDynamicSharedMemorySize, G10_SMEM);
        cudaFuncSetAttribute(gemm10<1>, cudaFuncAttributeMaxDynamicSharedMemorySize, G10_SMEM);
        cudaFuncSetAttribute(gemm10<2>, cudaFuncAttributeMaxDynamicSharedMemorySize, G10_SMEM);
        cudaFuncSetAttribute(attn_tc_kernel, cudaFuncAttributeMaxDynamicSharedMemorySize, ATTN_SMEM);
        attrDone = true;
    }

    // ---- attention path ----
    rmsnorm_kernel<<<T,256>>>(hidden, ln1, xnorm);
    {
        dim3 g(QKV_N/128, T/128, 1);
        gemm10<0><<<g,128,G10_SMEM>>>(xnorm, w_qkv, qkvb, T, QKV_N, H, nullptr, 0, nullptr, nullptr);
    }
    rope_kernel<<<T,256>>>(qkvb);
    {
        dim3 g(T/128, NH, 1);
        attn_tc_kernel<<<g,256,ATTN_SMEM>>>(qkvb, attnb);
    }
    {
        dim3 g(H/128, T/128, 1);
        gemm10<0><<<g,128,G10_SMEM>>>(attnb, w_o, resid_out, T, H, H, hidden, 0, nullptr, nullptr);
    }

    // ---- MoE path ----
    reset_kernel<<<1,32>>>();
    rmsnorm_router_kernel<<<T,256>>>(resid_out, ln2, gate_w, x2);
    scan_kernel<<<1,1>>>();
    scatter_kernel<<<(T+255)/256,256>>>();
    {
        dim3 g(FFN/128, T/128, 2*NE);
        gemm10<1><<<g,128,G10_SMEM>>>(x2, w1, h1, T, FFN, H, nullptr, (long)H*FFN, w3, h3);
    }
    silu_kernel<<<4096,256>>>();
    {
        dim3 g(H/128, T/128, NE);
        gemm10<2><<<g,128,G10_SMEM>>>(h1, w2, y, T, H, FFN, nullptr, (long)FFN*H, nullptr, nullptr);
    }
    combine_kernel<<<(T*H)/256,256>>>(final_out);
}

// round 17
// speedup vs baseline: 1.0439x; 1.0439x over previous
#include <cuda_runtime.h>
#include <cuda_fp16.h>
#include <math.h>
#include <stdint.h>

#define T 2048
#define H 2048
#define NH 32
#define NKV 8
#define HD 64
#define FFN 4096
#define NE 8
#define QKV_N 3072
#define ASSIGN (2*T)

// ---------------- scratch ----------------------------------------------------
__device__ float g_xnorm[T*H];
__device__ float g_qkv[(long)T*QKV_N];
__device__ float g_attn[(long)T*H];
__device__ float g_x2[(long)T*H];
__device__ float g_h1[(long)ASSIGN*FFN];
__device__ float g_h3[(long)ASSIGN*FFN];
__device__ float g_y[(long)ASSIGN*H];
__device__ int   g_counts[NE];
__device__ int   g_offs[NE];
__device__ int   g_fill[NE];
__device__ int   g_perm[ASSIGN];
__device__ float g_permw[ASSIGN];
__device__ int   g_tokpos[ASSIGN];
__device__ int   g_topid[T*2];
__device__ float g_topw[T*2];

// ---------------- helpers ------------------------------------------------------
__device__ __forceinline__ void mma_f16(float* c, const uint32_t* a, const uint32_t* b) {
    asm volatile(
        "mma.sync.aligned.m16n8k16.row.col.f32.f16.f16.f32 "
        "{%0,%1,%2,%3},{%4,%5,%6,%7},{%8,%9},{%0,%1,%2,%3};"
        : "+f"(c[0]), "+f"(c[1]), "+f"(c[2]), "+f"(c[3])
        : "r"(a[0]), "r"(a[1]), "r"(a[2]), "r"(a[3]), "r"(b[0]), "r"(b[1]));
}
__device__ __forceinline__ uint32_t packh2(float lo, float hi) {
    __half2 h = __floats2half2_rn(lo, hi);
    return *(uint32_t*)&h;
}
__device__ __forceinline__ uint32_t smem_u32(const void* p) {
    uint32_t a;
    asm("{ .reg .u64 t; cvta.to.shared.u64 t, %1; cvt.u32.u64 %0, t; }" : "=r"(a) : "l"(p));
    return a;
}

// ---------------- rmsnorm ------------------------------------------------------
__global__ __launch_bounds__(256) void rmsnorm_kernel(
    const float* __restrict__ x, const float* __restrict__ w, float* __restrict__ out)
{
    int t = blockIdx.x;
    const float* xr = x + (long)t*H;
    __shared__ float red[256];
    float s = 0.f;
    for (int h = threadIdx.x; h < H; h += 256) { float v = xr[h]; s += v*v; }
    red[threadIdx.x] = s; __syncthreads();
    for (int st = 128; st > 0; st >>= 1) {
        if (threadIdx.x < st) red[threadIdx.x] += red[threadIdx.x+st];
        __syncthreads();
    }
    float inv = rsqrtf(red[0]/(float)H + 1e-5f);
    float* orow = out + (long)t*H;
    for (int h = threadIdx.x; h < H; h += 256) orow[h] = xr[h]*inv*w[h];
}

// ---------------- rmsnorm + router (fused, bit-identical) -----------------------
__global__ __launch_bounds__(256) void rmsnorm_router_kernel(
    const float* __restrict__ x, const float* __restrict__ w,
    const float* __restrict__ gw, float* __restrict__ out)
{
    int t = blockIdx.x;
    const float* xr = x + (long)t*H;
    __shared__ float red[256];
    float s = 0.f;
    for (int h = threadIdx.x; h < H; h += 256) { float v = xr[h]; s += v*v; }
    red[threadIdx.x] = s; __syncthreads();
    for (int st = 128; st > 0; st >>= 1) {
        if (threadIdx.x < st) red[threadIdx.x] += red[threadIdx.x+st];
        __syncthreads();
    }
    float inv = rsqrtf(red[0]/(float)H + 1e-5f);
    __syncthreads();

    float* orow = out + (long)t*H;
    float p[NE] = {};
    for (int h = threadIdx.x; h < H; h += 256) {
        float v = xr[h]*inv*w[h];
        orow[h] = v;
        #pragma unroll
        for (int e = 0; e < NE; e++) p[e] += v * gw[h*NE + e];
    }
    __shared__ float red8[NE*256];
    #pragma unroll
    for (int e = 0; e < NE; e++) red8[e*256 + threadIdx.x] = p[e];
    __syncthreads();
    for (int st = 128; st > 0; st >>= 1) {
        if (threadIdx.x < st)
            #pragma unroll
            for (int e = 0; e < NE; e++)
                red8[e*256+threadIdx.x] += red8[e*256+threadIdx.x+st];
        __syncthreads();
    }
    if (threadIdx.x == 0) {
        float l[NE];
        #pragma unroll
        for (int e = 0; e < NE; e++) l[e] = red8[e*256];
        int i1 = 0;
        #pragma unroll
        for (int e = 1; e < NE; e++) if (l[e] > l[i1]) i1 = e;
        int i2 = -1;
        #pragma unroll
        for (int e = 0; e < NE; e++) if (e != i1 && (i2 < 0 || l[e] > l[i2])) i2 = e;
        float p2 = expf(l[i2] - l[i1]);
        float invw = 1.f / (1.f + p2);
        g_topid[2*t] = i1;   g_topid[2*t+1] = i2;
        g_topw[2*t]  = invw; g_topw[2*t+1]  = p2*invw;
        atomicAdd(&g_counts[i1], 1);
        atomicAdd(&g_counts[i2], 1);
    }
}

// ---------------- fp16 mma.sync GEMM: 128x128 CTA, 4 warps (2x2), 64x64 tiles ---
#define PAW 18
#define PBW 18
#define A10_WORDS (128*PAW)
#define B10_WORDS (128*PBW)
#define G10_SMEM ((2*(A10_WORDS+B10_WORDS))*4)

template<int MODE>
__global__ __launch_bounds__(128, 2) void gemm10(
    const float* __restrict__ A, const float* __restrict__ B, float* __restrict__ C,
    int M, int N, int K, const float* __restrict__ addsrc, long bStrideZ,
    const float* __restrict__ B3, float* __restrict__ C3)
{
    extern __shared__ uint32_t sm10[];
    int z = blockIdx.z;
    int mBase = blockIdx.y * 128;
    int nBase = blockIdx.x * 128;
    int Meff = M, rowOff = 0;
    if (MODE == 1 || MODE == 2) {
        int ze = (MODE == 1 && z >= NE) ? z - NE : z;
        if (MODE == 1 && z >= NE) { B = B3; C = C3; }
        Meff = g_counts[ze]; rowOff = g_offs[ze];
        if (mBase >= Meff) return;
        B += (long)ze * bStrideZ;
    }

    int tid = threadIdx.x, lane = tid & 31, wid = tid >> 5;
    int mW = (wid >> 1) * 64;
    int nW = (wid & 1) * 64;
    int g  = lane >> 2, t4 = lane & 3;

    uint32_t* smA = sm10;
    uint32_t* smB = sm10 + 2*A10_WORDS;

    int arow = tid >> 3;
    int ac   = tid & 7;
    const float* aPtr[8]; bool aOk[8];
    #pragma unroll
    for (int i = 0; i < 8; i++) {
        int gm = mBase + arow + 16*i;
        aOk[i] = gm < Meff;
        long r;
        if (MODE == 1)      r = aOk[i] ? (long)g_perm[rowOff + gm] : 0;
        else if (MODE == 2) r = (long)(rowOff + (aOk[i] ? gm : 0));
        else                r = (long)(aOk[i] ? gm : 0);
        aPtr[i] = A + r*(long)K + ac*4;
    }
    int nl = tid & 31;
    int kp = tid >> 5;
    const float* bPtr = B + nBase + nl;

    float acc[4][8][4];
    #pragma unroll
    for (int mt = 0; mt < 4; mt++)
        #pragma unroll
        for (int nt = 0; nt < 8; nt++)
            #pragma unroll
            for (int q = 0; q < 4; q++) acc[mt][nt][q] = 0.f;

    int KT = K >> 5;
    float4 aR[8];
    float bv0[4][4], bv1[4][4];

    #pragma unroll
    for (int i = 0; i < 8; i++)
        aR[i] = aOk[i] ? *(const float4*)(aPtr[i]) : make_float4(0.f,0.f,0.f,0.f);
    #pragma unroll
    for (int p = 0; p < 4; p++)
        #pragma unroll
        for (int j = 0; j < 4; j++) {
            long ko = (long)(2*(kp + 4*p))*N + 32*j;
            bv0[p][j] = bPtr[ko];
            bv1[p][j] = bPtr[ko + N];
        }
    #pragma unroll
    for (int i = 0; i < 8; i++) {
        uint2 u = { packh2(aR[i].x, aR[i].y), packh2(aR[i].z, aR[i].w) };
        *(uint2*)(smA + (arow + 16*i)*PAW + ac*2) = u;
    }
    #pragma unroll
    for (int p = 0; p < 4; p++)
        #pragma unroll
        for (int j = 0; j < 4; j++)
            smB[(nl + 32*j)*PBW + kp + 4*p] = packh2(bv0[p][j], bv1[p][j]);
    __syncthreads();

    for (int kt = 0; kt < KT; kt++) {
        int buf = kt & 1;
        int nb  = buf ^ 1;
        if (kt + 1 < KT) {
            int k0 = (kt + 1) << 5;
            #pragma unroll
            for (int i = 0; i < 8; i++)
                aR[i] = aOk[i] ? *(const float4*)(aPtr[i] + k0)
                               : make_float4(0.f,0.f,0.f,0.f);
            #pragma unroll
            for (int p = 0; p < 4; p++)
                #pragma unroll
                for (int j = 0; j < 4; j++) {
                    long ko = (long)(k0 + 2*(kp + 4*p))*N + 32*j;
                    bv0[p][j] = bPtr[ko];
                    bv1[p][j] = bPtr[ko + N];
                }
        }

        const uint32_t* as = smA + buf*A10_WORDS;
        const uint32_t* bs = smB + buf*B10_WORDS;

        #pragma unroll
        for (int s = 0; s < 2; s++) {
            uint32_t af[4][4], bf[8][2];
            #pragma unroll
            for (int mt = 0; mt < 4; mt++) {
                const uint32_t* p = as + (mW + mt*16 + g)*PAW + s*8 + t4;
                af[mt][0] = p[0];
                af[mt][1] = p[8*PAW];
                af[mt][2] = p[4];
                af[mt][3] = p[8*PAW + 4];
            }
            #pragma unroll
            for (int nt = 0; nt < 8; nt++) {
                const uint32_t* p = bs + (nW + nt*8 + g)*PBW + s*8 + t4;
                bf[nt][0] = p[0];
                bf[nt][1] = p[4];
            }
            #pragma unroll
            for (int mt = 0; mt < 4; mt++)
                #pragma unroll
                for (int nt = 0; nt < 8; nt++)
                    mma_f16(acc[mt][nt], af[mt], bf[nt]);
        }

        if (kt + 1 < KT) {
            uint32_t* dA = smA + nb*A10_WORDS;
            uint32_t* dB = smB + nb*B10_WORDS;
            #pragma unroll
            for (int i = 0; i < 8; i++) {
                uint2 u = { packh2(aR[i].x, aR[i].y), packh2(aR[i].z, aR[i].w) };
                *(uint2*)(dA + (arow + 16*i)*PAW + ac*2) = u;
            }
            #pragma unroll
            for (int p = 0; p < 4; p++)
                #pragma unroll
                for (int j = 0; j < 4; j++)
                    dB[(nl + 32*j)*PBW + kp + 4*p] = packh2(bv0[p][j], bv1[p][j]);
        }
        __syncthreads();
    }

    #pragma unroll
    for (int mt = 0; mt < 4; mt++) {
        #pragma unroll
        for (int half = 0; half < 2; half++) {
            int rRel = mW + mt*16 + g + half*8;
            bool ok = (MODE == 0) || (mBase + rRel < Meff);
            if (!ok) continue;
            long crow;
            float scale = 1.f;
            if (MODE == 0) crow = (long)(mBase + rRel);
            else           crow = (long)(rowOff + mBase + rRel);
            if (MODE == 2) scale = g_permw[rowOff + mBase + rRel];
            #pragma unroll
            for (int nt = 0; nt < 8; nt++) {
                int col = nBase + nW + nt*8 + t4*2;
                float v0 = acc[mt][nt][2*half + 0];
                float v1 = acc[mt][nt][2*half + 1];
                if (MODE == 2) { v0 *= scale; v1 *= scale; }
                if (MODE == 0 && addsrc) {
                    v0 += addsrc[crow*N + col];
                    v1 += addsrc[crow*N + col + 1];
                }
                *(float2*)(C + crow*N + col) = make_float2(v0, v1);
            }
        }
    }
}

// ---------------- RoPE (smem sincos table) --------------------------------------
__global__ __launch_bounds__(256) void rope_kernel(float* __restrict__ qkv)
{
    __shared__ float cs[32], sn[32];
    int t = blockIdx.x;
    float pos = (float)t;
    if (threadIdx.x < 32) {
        int j = threadIdx.x;
        float inv = expf(-((float)(2*j)/(float)HD) * logf(10000.0f));
        float f = pos * inv;
        cs[j] = cosf(f);
        sn[j] = sinf(f);
    }
    __syncthreads();
    for (int idx = threadIdx.x; idx < (NH+NKV)*32; idx += 256) {
        int head = idx >> 5;
        int j    = idx & 31;
        int colbase = (head < NH) ? head*HD : (NH*HD + (head-NH)*HD);
        float c = cs[j], s = sn[j];
        float* p = qkv + (long)t*QKV_N + colbase;
        float x1 = p[j], x2 = p[j+32];
        p[j]    = x1*c - x2*s;
        p[j+32] = x2*c + x1*s;
    }
}

// ---------------- flash attention: 64 q-rows/CTA, split-fp16 QK^T, fp16 PV -----
#define PH  36
#define PVW 35
#define PP  36
#define ATTN_SMEM ((4*64*PH + 64*PVW + 64*PP)*4)

__global__ __launch_bounds__(128, 4) void attn_tc_kernel(
    const float* __restrict__ qkv, float* __restrict__ attn)
{
    extern __shared__ uint32_t su[];
    uint32_t* sQh = su;
    uint32_t* sQl = sQh + 64*PH;
    uint32_t* sKh = sQl + 64*PH;
    uint32_t* sKl = sKh + 64*PH;
    uint32_t* sVt = sKl + 64*PH;
    uint32_t* sP  = sVt + 64*PVW;
    __half*   sVtH = (__half*)sVt;

    int h = blockIdx.y, qt = blockIdx.x;
    int kvh = h >> 2;
    int tid = threadIdx.x, lane = tid & 31, w = tid >> 5;
    int g = lane >> 2, t4 = lane & 3;
    int mRow = w*16 + g;

    for (int i = tid; i < 1024; i += 128) {
        int r = i >> 4, d4 = (i & 15) << 2;
        float4 v = *(const float4*)(qkv + (long)(qt*64 + r)*QKV_N + h*HD + d4);
        float q0 = v.x*0.125f, q1 = v.y*0.125f, q2 = v.z*0.125f, q3 = v.w*0.125f;
        __half h0 = __float2half_rn(q0), h1 = __float2half_rn(q1);
        __half h2 = __float2half_rn(q2), h3 = __float2half_rn(q3);
        float l0 = q0 - __half2float(h0), l1 = q1 - __half2float(h1);
        float l2 = q2 - __half2float(h2), l3 = q3 - __half2float(h3);
        __half2 p0 = __halves2half2(h0, h1), p1 = __halves2half2(h2, h3);
        uint2 uh = { *(uint32_t*)&p0, *(uint32_t*)&p1 };
        uint2 ul = { packh2(l0, l1), packh2(l2, l3) };
        *(uint2*)(sQh + r*PH + (d4 >> 1)) = uh;
        *(uint2*)(sQl + r*PH + (d4 >> 1)) = ul;
    }

    float m_a = -1e30f, m_b = -1e30f, l_a = 0.f, l_b = 0.f;
    float o[8][4];
    #pragma unroll
    for (int nt = 0; nt < 8; nt++)
        #pragma unroll
        for (int q = 0; q < 4; q++) o[nt][q] = 0.f;

    for (int kt = 0; kt <= qt; kt++) {
        __syncthreads();
        for (int i = tid; i < 1024; i += 128) {
            int r = i >> 4, d4 = (i & 15) << 2;
            const float* kp = qkv + (long)(kt*64 + r)*QKV_N + NH*HD + kvh*HD + d4;
            float4 kv = *(const float4*)kp;
            float4 vv = *(const float4*)(kp + NKV*HD);
            __half h0 = __float2half_rn(kv.x), h1 = __float2half_rn(kv.y);
            __half h2 = __float2half_rn(kv.z), h3 = __float2half_rn(kv.w);
            float l0 = kv.x - __half2float(h0), l1 = kv.y - __half2float(h1);
            float l2 = kv.z - __half2float(h2), l3 = kv.w - __half2float(h3);
            __half2 p0 = __halves2half2(h0, h1), p1 = __halves2half2(h2, h3);
            uint2 uh = { *(uint32_t*)&p0, *(uint32_t*)&p1 };
            uint2 ul = { packh2(l0, l1), packh2(l2, l3) };
            *(uint2*)(sKh + r*PH + (d4 >> 1)) = uh;
            *(uint2*)(sKl + r*PH + (d4 >> 1)) = ul;
            sVtH[(d4+0)*(2*PVW) + r] = __float2half_rn(vv.x);
            sVtH[(d4+1)*(2*PVW) + r] = __float2half_rn(vv.y);
            sVtH[(d4+2)*(2*PVW) + r] = __float2half_rn(vv.z);
            sVtH[(d4+3)*(2*PVW) + r] = __float2half_rn(vv.w);
        }
        __syncthreads();

        float s[8][4];
        #pragma unroll
        for (int nt = 0; nt < 8; nt++)
            #pragma unroll
            for (int q = 0; q < 4; q++) s[nt][q] = 0.f;

        #pragma unroll
        for (int ks = 0; ks < 4; ks++) {
            uint32_t ah[4], al[4];
            {
                const uint32_t* p = sQh + mRow*PH + ks*8 + t4;
                ah[0]=p[0]; ah[1]=p[8*PH]; ah[2]=p[4]; ah[3]=p[8*PH+4];
                const uint32_t* q2 = sQl + mRow*PH + ks*8 + t4;
                al[0]=q2[0]; al[1]=q2[8*PH]; al[2]=q2[4]; al[3]=q2[8*PH+4];
            }
            #pragma unroll
            for (int nt = 0; nt < 8; nt++) {
                uint32_t bh[2], bl[2];
                const uint32_t* p = sKh + (nt*8 + g)*PH + ks*8 + t4;
                bh[0] = p[0]; bh[1] = p[4];
                const uint32_t* q2 = sKl + (nt*8 + g)*PH + ks*8 + t4;
                bl[0] = q2[0]; bl[1] = q2[4];
                mma_f16(s[nt], ah, bh);
                mma_f16(s[nt], ah, bl);
                mma_f16(s[nt], al, bh);
            }
        }

        if (kt == qt) {
            #pragma unroll
            for (int nt = 0; nt < 8; nt++) {
                int c0 = nt*8 + 2*t4;
                if (c0     > mRow)   s[nt][0] = -1e30f;
                if (c0 + 1 > mRow)   s[nt][1] = -1e30f;
                if (c0     > mRow+8) s[nt][2] = -1e30f;
                if (c0 + 1 > mRow+8) s[nt][3] = -1e30f;
            }
        }

        float rma = -1e30f, rmb = -1e30f;
        #pragma unroll
        for (int nt = 0; nt < 8; nt++) {
            rma = fmaxf(rma, fmaxf(s[nt][0], s[nt][1]));
            rmb = fmaxf(rmb, fmaxf(s[nt][2], s[nt][3]));
        }
        rma = fmaxf(rma, __shfl_xor_sync(0xffffffffu, rma, 1));
        rma = fmaxf(rma, __shfl_xor_sync(0xffffffffu, rma, 2));
        rmb = fmaxf(rmb, __shfl_xor_sync(0xffffffffu, rmb, 1));
        rmb = fmaxf(rmb, __shfl_xor_sync(0xffffffffu, rmb, 2));

        float mna = fmaxf(m_a, rma), mnb = fmaxf(m_b, rmb);
        float suma = 0.f, sumb = 0.f;
        #pragma unroll
        for (int nt = 0; nt < 8; nt++) {
            s[nt][0] = __expf(s[nt][0] - mna); suma += s[nt][0];
            s[nt][1] = __expf(s[nt][1] - mna); suma += s[nt][1];
            s[nt][2] = __expf(s[nt][2] - mnb); sumb += s[nt][2];
            s[nt][3] = __expf(s[nt][3] - mnb); sumb += s[nt][3];
        }
        suma += __shfl_xor_sync(0xffffffffu, suma, 1);
        suma += __shfl_xor_sync(0xffffffffu, suma, 2);
        sumb += __shfl_xor_sync(0xffffffffu, sumb, 1);
        sumb += __shfl_xor_sync(0xffffffffu, sumb, 2);

        float alpa = __expf(m_a - mna), alpb = __expf(m_b - mnb);
        l_a = l_a*alpa + suma; m_a = mna;
        l_b = l_b*alpb + sumb; m_b = mnb;
        #pragma unroll
        for (int nt = 0; nt < 8; nt++) {
            o[nt][0] *= alpa; o[nt][1] *= alpa;
            o[nt][2] *= alpb; o[nt][3] *= alpb;
        }

        #pragma unroll
        for (int nt = 0; nt < 8; nt++) {
            sP[mRow*PP + nt*4 + t4]     = packh2(s[nt][0], s[nt][1]);
            sP[(mRow+8)*PP + nt*4 + t4] = packh2(s[nt][2], s[nt][3]);
        }
        __syncwarp();

        #pragma unroll
        for (int ks = 0; ks < 4; ks++) {
            uint32_t ap[4];
            const uint32_t* p = sP + mRow*PP + ks*8 + t4;
            ap[0]=p[0]; ap[1]=p[8*PP]; ap[2]=p[4]; ap[3]=p[8*PP+4];
            #pragma unroll
            for (int nt = 0; nt < 8; nt++) {
                uint32_t bv[2];
                const uint32_t* q = sVt + (nt*8 + g)*PVW + ks*8 + t4;
                bv[0] = q[0]; bv[1] = q[4];
                mma_f16(o[nt], ap, bv);
            }
        }
    }

    float inva = 1.f / l_a, invb = 1.f / l_b;
    #pragma unroll
    for (int nt = 0; nt < 8; nt++) {
        int col = h*HD + nt*8 + 2*t4;
        long ra = (long)(qt*64 + mRow);
        *(float2*)(attn + ra*H + col)     = make_float2(o[nt][0]*inva, o[nt][1]*inva);
        *(float2*)(attn + (ra+8)*H + col) = make_float2(o[nt][2]*invb, o[nt][3]*invb);
    }
}

// ---------------- MoE plumbing --------------------------------------------------
__global__ void reset_kernel() { if (threadIdx.x < NE) g_counts[threadIdx.x] = 0; }

__global__ void scan_kernel() {
    if (threadIdx.x == 0) {
        int s = 0;
        for (int e = 0; e < NE; e++) { g_offs[e] = s; g_fill[e] = s; s += g_counts[e]; }
    }
}

__global__ void scatter_kernel() {
    int t = blockIdx.x*256 + threadIdx.x;
    if (t >= T) return;
    #pragma unroll
    for (int k = 0; k < 2; k++) {
        int e = g_topid[2*t+k];
        int pos = atomicAdd(&g_fill[e], 1);
        g_perm[pos]  = t;
        g_permw[pos] = g_topw[2*t+k];
        g_tokpos[2*t+k] = pos;
    }
}

__global__ __launch_bounds__(256) void silu_kernel() {
    long n4 = (long)ASSIGN*FFN/4;
    const float4* h3v = (const float4*)g_h3;
    float4* h1v = (float4*)g_h1;
    for (long i = (long)blockIdx.x*256 + threadIdx.x; i < n4; i += (long)gridDim.x*256) {
        float4 a = h1v[i];
        float4 b = h3v[i];
        a.x = (a.x / (1.f + expf(-a.x))) * b.x;
        a.y = (a.y / (1.f + expf(-a.y))) * b.y;
        a.z = (a.z / (1.f + expf(-a.z))) * b.z;
        a.w = (a.w / (1.f + expf(-a.w))) * b.w;
        h1v[i] = a;
    }
}

__global__ __launch_bounds__(256) void combine_kernel(float* __restrict__ out) {
    int idx = blockIdx.x*256 + threadIdx.x;     // float4 index
    int t = idx >> 9;                            // H/4 = 512 per token
    int c = idx & 511;
    const float4* y0 = (const float4*)(g_y + (long)g_tokpos[2*t]*H);
    const float4* y1 = (const float4*)(g_y + (long)g_tokpos[2*t+1]*H);
    float4 a = y0[c], b = y1[c];
    a.x += b.x; a.y += b.y; a.z += b.z; a.w += b.w;
    ((float4*)out)[idx] = a;
}

// ---------------- launch --------------------------------------------------------
extern "C" void kernel_launch(void* const* d_in, const int* in_sizes, int n_in,
                              void* d_out, int out_size)
{
    const float* hidden = (const float*)d_in[0];
    const float* w_qkv  = (const float*)d_in[2];
    const float* w_o    = (const float*)d_in[3];
    const float* gate_w = (const float*)d_in[4];
    const float* w1     = (const float*)d_in[5];
    const float* w2     = (const float*)d_in[6];
    const float* w3     = (const float*)d_in[7];
    const float* ln1    = (const float*)d_in[8];
    const float* ln2    = (const float*)d_in[9];

    float* out       = (float*)d_out;
    float* final_out = out;
    float* resid_out = out + (long)T*H;

    float *xnorm, *qkvb, *attnb, *x2, *h1, *h3, *y;
    cudaGetSymbolAddress((void**)&xnorm, g_xnorm);
    cudaGetSymbolAddress((void**)&qkvb,  g_qkv);
    cudaGetSymbolAddress((void**)&attnb, g_attn);
    cudaGetSymbolAddress((void**)&x2,    g_x2);
    cudaGetSymbolAddress((void**)&h1,    g_h1);
    cudaGetSymbolAddress((void**)&h3,    g_h3);
    cudaGetSymbolAddress((void**)&y,     g_y);

    static bool attrDone = false;
    if (!attrDone) {
        cudaFuncSetAttribute(gemm10<0>, cudaFuncAttributeMaxDynamicSharedMemorySize, G10_SMEM);
        cudaFuncSetAttribute(gemm10<1>, cudaFuncAttributeMaxDynamicSharedMemorySize, G10_SMEM);
        cudaFuncSetAttribute(gemm10<2>, cudaFuncAttributeMaxDynamicSharedMemorySize, G10_SMEM);
        cudaFuncSetAttribute(attn_tc_kernel, cudaFuncAttributeMaxDynamicSharedMemorySize, ATTN_SMEM);
        attrDone = true;
    }

    // ---- attention path ----
    rmsnorm_kernel<<<T,256>>>(hidden, ln1, xnorm);
    {
        dim3 g(QKV_N/128, T/128, 1);
        gemm10<0><<<g,128,G10_SMEM>>>(xnorm, w_qkv, qkvb, T, QKV_N, H, nullptr, 0, nullptr, nullptr);
    }
    rope_kernel<<<T,256>>>(qkvb);
    {
        dim3 g(T/64, NH, 1);
        attn_tc_kernel<<<g,128,ATTN_SMEM>>>(qkvb, attnb);
    }
    {
        dim3 g(H/128, T/128, 1);
        gemm10<0><<<g,128,G10_SMEM>>>(attnb, w_o, resid_out, T, H, H, hidden, 0, nullptr, nullptr);
    }

    // ---- MoE path ----
    reset_kernel<<<1,32>>>();
    rmsnorm_router_kernel<<<T,256>>>(resid_out, ln2, gate_w, x2);
    scan_kernel<<<1,1>>>();
    scatter_kernel<<<(T+255)/256,256>>>();
    {
        dim3 g(FFN/128, T/128, 2*NE);
        gemm10<1><<<g,128,G10_SMEM>>>(x2, w1, h1, T, FFN, H, nullptr, (long)H*FFN, w3, h3);
    }
    silu_kernel<<<2048,256>>>();
    {
        dim3 g(H/128, T/128, NE);
        gemm10<2><<<g,128,G10_SMEM>>>(h1, w2, y, T, H, FFN, nullptr, (long)FFN*H, nullptr, nullptr);
    }
    combine_kernel<<<(T*H/4)/256,256>>>(final_out);
}